// round 3
// baseline (speedup 1.0000x reference)
#include <cuda_runtime.h>
#include <cuda_bf16.h>
#include <mma.h>
#include <math.h>

using namespace nvcuda;

#define SEQ 12
#define D 1024
#define H 16
#define HD 64
#define BATCH 4096
#define NROWS (BATCH * SEQ)   // 49152
#define EPS 1e-5f

// ---------------- scratch (no allocations allowed) ----------------
__device__ float g_q[NROWS * D];
__device__ float g_k[NROWS * D];
__device__ float g_v[NROWS * D];
__device__ float g_att[NROWS * D];
__device__ float g_proj[NROWS * D];
__device__ float g_mask[SEQ * SEQ];

// ---------------- edge mask (dtype-sniffing: int32 vs int64 payload) ----------------
// JAX with x64 disabled materializes "int64" edge_index as int32. We read the
// raw buffer as int32 and detect: int64 little-endian data of small values has
// ALL odd int32 words == 0 (high words). int32 data has random column indices
// at odd positions, so some are nonzero.
__global__ void mask_kernel(const int* __restrict__ e32, int n_elems) {
    __shared__ int is64;
    int tid = threadIdx.x;
    if (tid == 0) {
        int all_odd_zero = 1;
        for (int i = 1; i < n_elems; i += 2)
            if (e32[i] != 0) { all_odd_zero = 0; break; }
        is64 = all_odd_zero;
    }
    if (tid < SEQ * SEQ) g_mask[tid] = 0.0f;
    __syncthreads();
    int n_edges = n_elems / 2;   // n_elems = element count (pairs of values)
    for (int t = tid; t < n_edges; t += blockDim.x) {
        int r, c;
        if (is64) { r = e32[4 * t]; c = e32[4 * t + 2]; }
        else      { r = e32[2 * t]; c = e32[2 * t + 1]; }
        if (r >= 0 && r < SEQ && c >= 0 && c < SEQ)
            g_mask[r * SEQ + c] = 1.0f;   // benign write race, all write 1.0
    }
}

// ---------------- TF32 GEMM: C = A @ B   (A: MxK row, B: KxN row) ----------------
#define BM 128
#define BN 128
#define BK 32
#define LDA_S 36    // BK + 4 pad
#define LDB_S 132   // BN + 4 pad

__global__ void __launch_bounds__(256) gemm_tf32(const float* __restrict__ A,
                                                 const float* __restrict__ B,
                                                 float* __restrict__ C,
                                                 int M, int N, int K) {
    __shared__ float As[BM * LDA_S];  // 18 KB
    __shared__ float Bs[BK * LDB_S];  // 16.5 KB

    const int tid = threadIdx.x;
    const int wid = tid >> 5;
    const int wm  = wid >> 2;       // 0..1  -> 64 rows each
    const int wn  = wid & 3;        // 0..3  -> 32 cols each
    const int brow = blockIdx.y * BM;
    const int bcol = blockIdx.x * BN;

    wmma::fragment<wmma::accumulator, 16, 16, 8, float> acc[4][2];
    #pragma unroll
    for (int m = 0; m < 4; m++)
        #pragma unroll
        for (int n = 0; n < 2; n++)
            wmma::fill_fragment(acc[m][n], 0.0f);

    const int ktiles = K / BK;
    for (int kt = 0; kt < ktiles; kt++) {
        __syncthreads();
        // stage A tile: BM x BK (1024 float4s over 256 threads)
        {
            const float* Ag = A + (long)brow * K + kt * BK;
            #pragma unroll
            for (int i = 0; i < 4; i++) {
                int idx = tid + i * 256;
                int r = idx >> 3;            // 8 float4 per row
                int c4 = (idx & 7) << 2;
                float4 v = *(const float4*)(Ag + (long)r * K + c4);
                float* dst = &As[r * LDA_S + c4];
                dst[0] = wmma::__float_to_tf32(v.x);
                dst[1] = wmma::__float_to_tf32(v.y);
                dst[2] = wmma::__float_to_tf32(v.z);
                dst[3] = wmma::__float_to_tf32(v.w);
            }
        }
        // stage B tile: BK x BN
        {
            const float* Bg = B + (long)(kt * BK) * N + bcol;
            #pragma unroll
            for (int i = 0; i < 4; i++) {
                int idx = tid + i * 256;
                int r = idx >> 5;            // 32 float4 per row
                int c4 = (idx & 31) << 2;
                float4 v = *(const float4*)(Bg + (long)r * N + c4);
                float* dst = &Bs[r * LDB_S + c4];
                dst[0] = wmma::__float_to_tf32(v.x);
                dst[1] = wmma::__float_to_tf32(v.y);
                dst[2] = wmma::__float_to_tf32(v.z);
                dst[3] = wmma::__float_to_tf32(v.w);
            }
        }
        __syncthreads();

        #pragma unroll
        for (int ks = 0; ks < 4; ks++) {
            int k0 = ks * 8;
            wmma::fragment<wmma::matrix_a, 16, 16, 8, wmma::precision::tf32, wmma::row_major> af[4];
            wmma::fragment<wmma::matrix_b, 16, 16, 8, wmma::precision::tf32, wmma::row_major> bf[2];
            #pragma unroll
            for (int m = 0; m < 4; m++)
                wmma::load_matrix_sync(af[m], &As[(wm * 64 + m * 16) * LDA_S + k0], LDA_S);
            #pragma unroll
            for (int n = 0; n < 2; n++)
                wmma::load_matrix_sync(bf[n], &Bs[k0 * LDB_S + wn * 32 + n * 16], LDB_S);
            #pragma unroll
            for (int m = 0; m < 4; m++)
                #pragma unroll
                for (int n = 0; n < 2; n++)
                    wmma::mma_sync(acc[m][n], af[m], bf[n], acc[m][n]);
        }
    }

    #pragma unroll
    for (int m = 0; m < 4; m++)
        #pragma unroll
        for (int n = 0; n < 2; n++) {
            float* cp = C + (long)(brow + wm * 64 + m * 16) * N + bcol + wn * 32 + n * 16;
            wmma::store_matrix_sync(cp, acc[m][n], N, wmma::mem_row_major);
        }
}

// ---------------- fused masked attention per (b, h) ----------------
__global__ void __launch_bounds__(128) attn_kernel(const float* __restrict__ bq,
                                                   const float* __restrict__ bk,
                                                   const float* __restrict__ bv) {
    const int bh = blockIdx.x;
    const int b = bh >> 4;
    const int h = bh & 15;
    __shared__ float qs[SEQ][HD];
    __shared__ float ks[SEQ][HD];
    __shared__ float vs[SEQ][HD];
    __shared__ float sc[SEQ][SEQ];

    const int tid = threadIdx.x;
    const long base = (long)(b * SEQ) * D + h * HD;

    for (int i = tid; i < SEQ * HD; i += 128) {
        int s = i >> 6, d = i & 63;
        long off = base + (long)s * D + d;
        qs[s][d] = g_q[off] + bq[h * HD + d];
        ks[s][d] = g_k[off] + bk[h * HD + d];
        vs[s][d] = g_v[off] + bv[h * HD + d];
    }
    __syncthreads();

    for (int t = tid; t < SEQ * SEQ; t += 128) {
        int i = t / SEQ, j = t % SEQ;
        float s = 0.0f;
        #pragma unroll
        for (int d = 0; d < HD; d++) s += qs[i][d] * ks[j][d];
        sc[i][j] = (g_mask[i * SEQ + j] == 0.0f) ? -INFINITY : s * 0.125f;
    }
    __syncthreads();

    if (tid < SEQ) {
        float mx = -INFINITY;
        #pragma unroll
        for (int j = 0; j < SEQ; j++) mx = fmaxf(mx, sc[tid][j]);
        float sum = 0.0f;
        #pragma unroll
        for (int j = 0; j < SEQ; j++) {
            float e = expf(sc[tid][j] - mx);
            sc[tid][j] = e;
            sum += e;
        }
        float inv = 1.0f / sum;
        #pragma unroll
        for (int j = 0; j < SEQ; j++) sc[tid][j] *= inv;
    }
    __syncthreads();

    for (int i = tid; i < SEQ * HD; i += 128) {
        int s = i >> 6, d = i & 63;
        float acc = 0.0f;
        #pragma unroll
        for (int j = 0; j < SEQ; j++) acc += sc[s][j] * vs[j][d];
        g_att[base + (long)s * D + d] = acc;
    }
}

// ---------------- bias + residual + LayerNorm ----------------
__global__ void __launch_bounds__(256) ln_kernel(const float* __restrict__ x,
                                                 const float* __restrict__ bo,
                                                 const float* __restrict__ gamma,
                                                 const float* __restrict__ beta,
                                                 float* __restrict__ out) {
    const int row = blockIdx.x;
    const float* p = g_proj + (long)row * D;
    const float* xr = x + (long)row * D;
    __shared__ float red[32];
    const int tid = threadIdx.x;
    const int lane = tid & 31, w = tid >> 5;

    float vals[4];
    float sum = 0.0f;
    #pragma unroll
    for (int i = 0; i < 4; i++) {
        int c = tid + i * 256;
        float hv = p[c] + bo[c] + xr[c];
        vals[i] = hv;
        sum += hv;
    }
    // block reduce (sum)
    #pragma unroll
    for (int o = 16; o; o >>= 1) sum += __shfl_xor_sync(~0u, sum, o);
    if (lane == 0) red[w] = sum;
    __syncthreads();
    if (w == 0) {
        float v = (lane < 8) ? red[lane] : 0.0f;
        #pragma unroll
        for (int o = 16; o; o >>= 1) v += __shfl_xor_sync(~0u, v, o);
        if (lane == 0) red[0] = v;
    }
    __syncthreads();
    const float mu = red[0] * (1.0f / D);
    __syncthreads();

    float vsum = 0.0f;
    #pragma unroll
    for (int i = 0; i < 4; i++) {
        float d0 = vals[i] - mu;
        vsum += d0 * d0;
    }
    #pragma unroll
    for (int o = 16; o; o >>= 1) vsum += __shfl_xor_sync(~0u, vsum, o);
    if (lane == 0) red[w] = vsum;
    __syncthreads();
    if (w == 0) {
        float v = (lane < 8) ? red[lane] : 0.0f;
        #pragma unroll
        for (int o = 16; o; o >>= 1) v += __shfl_xor_sync(~0u, v, o);
        if (lane == 0) red[0] = v;
    }
    __syncthreads();
    const float inv = rsqrtf(red[0] * (1.0f / D) + EPS);

    #pragma unroll
    for (int i = 0; i < 4; i++) {
        int c = tid + i * 256;
        out[(long)row * D + c] = (vals[i] - mu) * inv * gamma[c] + beta[c];
    }
}

// ---------------- launcher ----------------
extern "C" void kernel_launch(void* const* d_in, const int* in_sizes, int n_in,
                              void* d_out, int out_size) {
    const float* x     = (const float*)d_in[0];
    const int*   edge  = (const int*)d_in[1];
    const float* Wq    = (const float*)d_in[2];
    const float* bq    = (const float*)d_in[3];
    const float* Wk    = (const float*)d_in[4];
    const float* bk    = (const float*)d_in[5];
    const float* Wv    = (const float*)d_in[6];
    const float* bv    = (const float*)d_in[7];
    const float* Wo    = (const float*)d_in[8];
    const float* bo    = (const float*)d_in[9];
    const float* gamma = (const float*)d_in[10];
    const float* beta  = (const float*)d_in[11];
    float* out = (float*)d_out;

    float *qp, *kp, *vp, *ap, *pp;
    cudaGetSymbolAddress((void**)&qp, g_q);
    cudaGetSymbolAddress((void**)&kp, g_k);
    cudaGetSymbolAddress((void**)&vp, g_v);
    cudaGetSymbolAddress((void**)&ap, g_att);
    cudaGetSymbolAddress((void**)&pp, g_proj);

    mask_kernel<<<1, 256>>>(edge, in_sizes[1]);

    dim3 grid(D / BN, NROWS / BM);   // (8, 384)
    gemm_tf32<<<grid, 256>>>(x, Wq, qp, NROWS, D, D);
    gemm_tf32<<<grid, 256>>>(x, Wk, kp, NROWS, D, D);
    gemm_tf32<<<grid, 256>>>(x, Wv, vp, NROWS, D, D);

    attn_kernel<<<BATCH * H, 128>>>(bq, bk, bv);

    gemm_tf32<<<grid, 256>>>(ap, Wo, pp, NROWS, D, D);

    ln_kernel<<<NROWS, 256>>>(x, bo, gamma, beta, out);
}

// round 7
// speedup vs baseline: 1.3215x; 1.3215x over previous
#include <cuda_runtime.h>
#include <cuda_bf16.h>
#include <mma.h>
#include <math.h>
#include <cstdint>

using namespace nvcuda;

#define SEQ 12
#define D 1024
#define H 16
#define HD 64
#define BATCH 4096
#define NROWS (BATCH * SEQ)   // 49152
#define EPS 1e-5f

// ---------------- scratch (no allocations allowed) ----------------
__device__ float g_q[NROWS * D];
__device__ float g_k[NROWS * D];
__device__ float g_v[NROWS * D];
__device__ float g_att[NROWS * D];
__device__ float g_proj[NROWS * D];
__device__ float g_xc[NROWS * D];     // tf32-rounded x
__device__ float g_wq[D * D];
__device__ float g_wk[D * D];
__device__ float g_wv[D * D];
__device__ float g_wo[D * D];
__device__ float g_mask[SEQ * SEQ];

// ---------------- edge mask (dtype-sniffing: int32 vs int64 payload) ----------------
__global__ void mask_kernel(const int* __restrict__ e32, int n_elems) {
    __shared__ int is64;
    int tid = threadIdx.x;
    if (tid == 0) {
        int all_odd_zero = 1;
        for (int i = 1; i < n_elems; i += 2)
            if (e32[i] != 0) { all_odd_zero = 0; break; }
        is64 = all_odd_zero;
    }
    if (tid < SEQ * SEQ) g_mask[tid] = 0.0f;
    __syncthreads();
    int n_edges = n_elems / 2;
    for (int t = tid; t < n_edges; t += blockDim.x) {
        int r, c;
        if (is64) { r = e32[4 * t]; c = e32[4 * t + 2]; }
        else      { r = e32[2 * t]; c = e32[2 * t + 1]; }
        if (r >= 0 && r < SEQ && c >= 0 && c < SEQ)
            g_mask[r * SEQ + c] = 1.0f;
    }
}

// ---------------- tf32 pre-rounding (vectorized) ----------------
__global__ void __launch_bounds__(256) round_tf32(const float* __restrict__ in,
                                                  float* __restrict__ out, int n4) {
    int i = blockIdx.x * blockDim.x + threadIdx.x;
    if (i < n4) {
        float4 v = ((const float4*)in)[i];
        v.x = wmma::__float_to_tf32(v.x);
        v.y = wmma::__float_to_tf32(v.y);
        v.z = wmma::__float_to_tf32(v.z);
        v.w = wmma::__float_to_tf32(v.w);
        ((float4*)out)[i] = v;
    }
}

// ---------------- cp.async helpers ----------------
__device__ __forceinline__ void cp16(float* smem_dst, const float* gmem_src) {
    unsigned int d = (unsigned int)__cvta_generic_to_shared(smem_dst);
    asm volatile("cp.async.cg.shared.global [%0], [%1], 16;\n" :: "r"(d), "l"(gmem_src));
}
__device__ __forceinline__ void cp_commit() {
    asm volatile("cp.async.commit_group;\n");
}
template <int N>
__device__ __forceinline__ void cp_wait() {
    asm volatile("cp.async.wait_group %0;\n" :: "n"(N));
}

// ---------------- pipelined TF32 GEMM: C = A @ B (inputs pre-rounded) ----------------
// BM=128, BN=256, BK=32, 256 threads (8 warps, 2x4), 3-stage cp.async pipeline.
#define BM 128
#define BN 256
#define BK 32
#define LDA_S 36            // BK + 4
#define LDB_S 264           // BN + 8
#define SA (BM * LDA_S)     // 4608 floats
#define SB (BK * LDB_S)     // 8448 floats
#define STAGES 3
#define GEMM_SMEM ((STAGES * (SA + SB)) * 4)   // 156,672 bytes

__global__ void __launch_bounds__(256) gemm_tf32(const float* __restrict__ A,
                                                 const float* __restrict__ B,
                                                 float* __restrict__ C,
                                                 int M, int N, int K) {
    extern __shared__ float sm[];
    float* As = sm;
    float* Bs = sm + STAGES * SA;

    const int tid = threadIdx.x;
    const int wid = tid >> 5;
    const int wm  = wid >> 2;        // 0..1 -> 64 rows
    const int wn  = wid & 3;         // 0..3 -> 64 cols
    const long brow = (long)blockIdx.y * BM;
    const long bcol = (long)blockIdx.x * BN;

    wmma::fragment<wmma::accumulator, 16, 16, 8, float> acc[4][4];
    #pragma unroll
    for (int m = 0; m < 4; m++)
        #pragma unroll
        for (int n = 0; n < 4; n++)
            wmma::fill_fragment(acc[m][n], 0.0f);

    const int ktiles = K / BK;

    auto issue = [&](int kt, int buf) {
        float* ad = As + buf * SA;
        const float* Ag = A + brow * K + (long)kt * BK;
        #pragma unroll
        for (int i = 0; i < 4; i++) {
            int idx = tid + i * 256;          // 0..1023
            int r  = idx >> 3;                // 0..127
            int c4 = (idx & 7) << 2;          // 0..28
            cp16(ad + r * LDA_S + c4, Ag + (long)r * K + c4);
        }
        float* bd = Bs + buf * SB;
        const float* Bg = B + (long)kt * BK * N + bcol;
        #pragma unroll
        for (int i = 0; i < 8; i++) {
            int idx = tid + i * 256;          // 0..2047
            int r  = idx >> 6;                // 0..31
            int c4 = (idx & 63) << 2;         // 0..252
            cp16(bd + r * LDB_S + c4, Bg + (long)r * N + c4);
        }
    };

    // prologue: stages 0 and 1
    issue(0, 0); cp_commit();
    issue(1, 1); cp_commit();

    for (int kt = 0; kt < ktiles; kt++) {
        cp_wait<1>();
        __syncthreads();

        // issue stage kt+2 (may be empty) — overlaps with compute below
        if (kt + 2 < ktiles) issue(kt + 2, (kt + 2) % STAGES);
        cp_commit();

        const float* a = As + (kt % STAGES) * SA;
        const float* b = Bs + (kt % STAGES) * SB;
        #pragma unroll
        for (int ks = 0; ks < 4; ks++) {
            const int k0 = ks * 8;
            wmma::fragment<wmma::matrix_a, 16, 16, 8, wmma::precision::tf32, wmma::row_major> af[4];
            wmma::fragment<wmma::matrix_b, 16, 16, 8, wmma::precision::tf32, wmma::row_major> bf[4];
            #pragma unroll
            for (int m = 0; m < 4; m++)
                wmma::load_matrix_sync(af[m], a + (wm * 64 + m * 16) * LDA_S + k0, LDA_S);
            #pragma unroll
            for (int n = 0; n < 4; n++)
                wmma::load_matrix_sync(bf[n], b + k0 * LDB_S + wn * 64 + n * 16, LDB_S);
            #pragma unroll
            for (int m = 0; m < 4; m++)
                #pragma unroll
                for (int n = 0; n < 4; n++)
                    wmma::mma_sync(acc[m][n], af[m], bf[n], acc[m][n]);
        }
        __syncthreads();
    }

    #pragma unroll
    for (int m = 0; m < 4; m++)
        #pragma unroll
        for (int n = 0; n < 4; n++) {
            float* cp = C + (brow + wm * 64 + m * 16) * N + bcol + wn * 64 + n * 16;
            wmma::store_matrix_sync(cp, acc[m][n], N, wmma::mem_row_major);
        }
}

// ---------------- fused masked attention per (b, h) ----------------
__global__ void __launch_bounds__(128) attn_kernel(const float* __restrict__ bq,
                                                   const float* __restrict__ bk,
                                                   const float* __restrict__ bv) {
    const int bh = blockIdx.x;
    const int b = bh >> 4;
    const int h = bh & 15;
    __shared__ float qs[SEQ][HD];
    __shared__ float ks[SEQ][HD];
    __shared__ float vs[SEQ][HD];
    __shared__ float sc[SEQ][SEQ];

    const int tid = threadIdx.x;
    const long base = (long)(b * SEQ) * D + h * HD;

    for (int i = tid; i < SEQ * HD; i += 128) {
        int s = i >> 6, d = i & 63;
        long off = base + (long)s * D + d;
        qs[s][d] = g_q[off] + bq[h * HD + d];
        ks[s][d] = g_k[off] + bk[h * HD + d];
        vs[s][d] = g_v[off] + bv[h * HD + d];
    }
    __syncthreads();

    for (int t = tid; t < SEQ * SEQ; t += 128) {
        int i = t / SEQ, j = t % SEQ;
        float s = 0.0f;
        #pragma unroll
        for (int d = 0; d < HD; d++) s += qs[i][d] * ks[j][d];
        sc[i][j] = (g_mask[i * SEQ + j] == 0.0f) ? -INFINITY : s * 0.125f;
    }
    __syncthreads();

    if (tid < SEQ) {
        float mx = -INFINITY;
        #pragma unroll
        for (int j = 0; j < SEQ; j++) mx = fmaxf(mx, sc[tid][j]);
        float sum = 0.0f;
        #pragma unroll
        for (int j = 0; j < SEQ; j++) {
            float e = expf(sc[tid][j] - mx);
            sc[tid][j] = e;
            sum += e;
        }
        float inv = 1.0f / sum;
        #pragma unroll
        for (int j = 0; j < SEQ; j++) sc[tid][j] *= inv;
    }
    __syncthreads();

    for (int i = tid; i < SEQ * HD; i += 128) {
        int s = i >> 6, d = i & 63;
        float acc = 0.0f;
        #pragma unroll
        for (int j = 0; j < SEQ; j++) acc += sc[s][j] * vs[j][d];
        // write pre-rounded to tf32 so the Wo GEMM can cp.async it raw
        g_att[base + (long)s * D + d] = wmma::__float_to_tf32(acc);
    }
}

// ---------------- bias + residual + LayerNorm ----------------
__global__ void __launch_bounds__(256) ln_kernel(const float* __restrict__ x,
                                                 const float* __restrict__ bo,
                                                 const float* __restrict__ gamma,
                                                 const float* __restrict__ beta,
                                                 float* __restrict__ out) {
    const int row = blockIdx.x;
    const float* p = g_proj + (long)row * D;
    const float* xr = x + (long)row * D;
    __shared__ float red[32];
    const int tid = threadIdx.x;
    const int lane = tid & 31, w = tid >> 5;

    float vals[4];
    float sum = 0.0f;
    #pragma unroll
    for (int i = 0; i < 4; i++) {
        int c = tid + i * 256;
        float hv = p[c] + bo[c] + xr[c];
        vals[i] = hv;
        sum += hv;
    }
    #pragma unroll
    for (int o = 16; o; o >>= 1) sum += __shfl_xor_sync(~0u, sum, o);
    if (lane == 0) red[w] = sum;
    __syncthreads();
    if (w == 0) {
        float v = (lane < 8) ? red[lane] : 0.0f;
        #pragma unroll
        for (int o = 16; o; o >>= 1) v += __shfl_xor_sync(~0u, v, o);
        if (lane == 0) red[0] = v;
    }
    __syncthreads();
    const float mu = red[0] * (1.0f / D);
    __syncthreads();

    float vsum = 0.0f;
    #pragma unroll
    for (int i = 0; i < 4; i++) {
        float d0 = vals[i] - mu;
        vsum += d0 * d0;
    }
    #pragma unroll
    for (int o = 16; o; o >>= 1) vsum += __shfl_xor_sync(~0u, vsum, o);
    if (lane == 0) red[w] = vsum;
    __syncthreads();
    if (w == 0) {
        float v = (lane < 8) ? red[lane] : 0.0f;
        #pragma unroll
        for (int o = 16; o; o >>= 1) v += __shfl_xor_sync(~0u, v, o);
        if (lane == 0) red[0] = v;
    }
    __syncthreads();
    const float inv = rsqrtf(red[0] * (1.0f / D) + EPS);

    #pragma unroll
    for (int i = 0; i < 4; i++) {
        int c = tid + i * 256;
        out[(long)row * D + c] = (vals[i] - mu) * inv * gamma[c] + beta[c];
    }
}

// ---------------- launcher ----------------
extern "C" void kernel_launch(void* const* d_in, const int* in_sizes, int n_in,
                              void* d_out, int out_size) {
    const float* x     = (const float*)d_in[0];
    const int*   edge  = (const int*)d_in[1];
    const float* Wq    = (const float*)d_in[2];
    const float* bq    = (const float*)d_in[3];
    const float* Wk    = (const float*)d_in[4];
    const float* bk    = (const float*)d_in[5];
    const float* Wv    = (const float*)d_in[6];
    const float* bv    = (const float*)d_in[7];
    const float* Wo    = (const float*)d_in[8];
    const float* bo    = (const float*)d_in[9];
    const float* gamma = (const float*)d_in[10];
    const float* beta  = (const float*)d_in[11];
    float* out = (float*)d_out;

    float *qp, *kp, *vp, *ap, *pp, *xc, *wq, *wk, *wv, *wo;
    cudaGetSymbolAddress((void**)&qp, g_q);
    cudaGetSymbolAddress((void**)&kp, g_k);
    cudaGetSymbolAddress((void**)&vp, g_v);
    cudaGetSymbolAddress((void**)&ap, g_att);
    cudaGetSymbolAddress((void**)&pp, g_proj);
    cudaGetSymbolAddress((void**)&xc, g_xc);
    cudaGetSymbolAddress((void**)&wq, g_wq);
    cudaGetSymbolAddress((void**)&wk, g_wk);
    cudaGetSymbolAddress((void**)&wv, g_wv);
    cudaGetSymbolAddress((void**)&wo, g_wo);

    cudaFuncSetAttribute(gemm_tf32, cudaFuncAttributeMaxDynamicSharedMemorySize, GEMM_SMEM);

    mask_kernel<<<1, 256>>>(edge, in_sizes[1]);

    // pre-round operands to tf32 (RN) once
    const int XN4 = NROWS * D / 4;
    const int WN4 = D * D / 4;
    round_tf32<<<(XN4 + 255) / 256, 256>>>(x, xc, XN4);
    round_tf32<<<(WN4 + 255) / 256, 256>>>(Wq, wq, WN4);
    round_tf32<<<(WN4 + 255) / 256, 256>>>(Wk, wk, WN4);
    round_tf32<<<(WN4 + 255) / 256, 256>>>(Wv, wv, WN4);
    round_tf32<<<(WN4 + 255) / 256, 256>>>(Wo, wo, WN4);

    dim3 grid(D / BN, NROWS / BM);   // (4, 384)
    gemm_tf32<<<grid, 256, GEMM_SMEM>>>(xc, wq, qp, NROWS, D, D);
    gemm_tf32<<<grid, 256, GEMM_SMEM>>>(xc, wk, kp, NROWS, D, D);
    gemm_tf32<<<grid, 256, GEMM_SMEM>>>(xc, wv, vp, NROWS, D, D);

    attn_kernel<<<BATCH * H, 128>>>(bq, bk, bv);

    gemm_tf32<<<grid, 256, GEMM_SMEM>>>(ap, wo, pp, NROWS, D, D);

    ln_kernel<<<NROWS, 256>>>(x, bo, gamma, beta, out);
}